// round 6
// baseline (speedup 1.0000x reference)
#include <cuda_runtime.h>
#include <cstdint>

// Problem constants (fixed shapes from reference)
#define BN   32      // batch
#define DN   256     // feature dim
#define KN   1024    // codebook size
#define HWN  1024    // H*W
#define NN   32768   // B*H*W queries

// Tiling for the main GEMM-argmin kernel
#define TM 128   // queries per CTA tile
#define TK 128   // codes per CTA tile
#define TD 32    // d-chunk
#define APAD 4   // smem row padding (floats)

// Scratch (device globals: no allocation allowed)
__device__ unsigned long long g_best[NN];  // packed (scoreKey<<32)|codeIdx, min-reduced
__device__ float g_w2[KN];
__device__ float g_x2[NN];

// ---------------------------------------------------------------------------
// Init packed-best array to +inf
__global__ void vq_init_best() {
    int i = blockIdx.x * blockDim.x + threadIdx.x;
    if (i < NN) g_best[i] = 0xFFFFFFFFFFFFFFFFULL;
}

// w2[k] = sum_d weight[k,d]^2  (one warp per code row, coalesced).
// Square-then-add (rounded product), like jnp.sum(w*w): NOT fma.
__global__ void vq_w2(const float* __restrict__ w) {
    int k = blockIdx.x * 8 + (threadIdx.x >> 5);
    int lane = threadIdx.x & 31;
    if (k >= KN) return;
    const float* row = w + (size_t)k * DN;
    float s = 0.f;
    #pragma unroll
    for (int d = lane; d < DN; d += 32) {
        float v = row[d];
        s = __fadd_rn(s, __fmul_rn(v, v));
    }
    #pragma unroll
    for (int o = 16; o > 0; o >>= 1) s += __shfl_xor_sync(0xffffffffu, s, o);
    if (lane == 0) g_w2[k] = s;
}

// x2[n] = sum_d x[b,d,hw]^2 ; threads over hw (coalesced per d-step).
// Sequential in-order d=0..255, square rounded separately from the add,
// mimicking jnp.sum(xf*xf, axis=1) as closely as a fixed order can.
__global__ void vq_x2(const float* __restrict__ x) {
    int b   = blockIdx.y;
    int hw  = blockIdx.x * blockDim.x + threadIdx.x;
    const float* base = x + (size_t)b * DN * HWN + hw;
    float s = 0.f;
    #pragma unroll 8
    for (int d = 0; d < DN; d++) {
        float v = base[(size_t)d * HWN];
        s = __fadd_rn(s, __fmul_rn(v, v));
    }
    g_x2[b * HWN + hw] = s;
}

// ---------------------------------------------------------------------------
// Main: per CTA compute S[TKxTM] = W_tile . X_tile (fp32 FFMA GEMM),
// then d2 = (x2 - 2*dot) + w2, pack, reduce, atomicMin into g_best.
__global__ __launch_bounds__(256, 2)
void vq_main(const float* __restrict__ x, const float* __restrict__ w) {
    __shared__ __align__(16) float As[TD][TK + APAD];  // [d][k]
    __shared__ __align__(16) float Bs[TD][TM + APAD];  // [d][m]

    const int b  = blockIdx.z;
    const int k0 = blockIdx.y * TK;
    const int m0 = blockIdx.x * TM;
    const float* Xb = x + (size_t)b * DN * HWN;

    const int tid = threadIdx.x;
    const int tx  = tid & 15;   // m micro-tile
    const int ty  = tid >> 4;   // k micro-tile

    float acc[8][8];
    #pragma unroll
    for (int i = 0; i < 8; i++)
        #pragma unroll
        for (int j = 0; j < 8; j++) acc[i][j] = 0.f;

    for (int d0 = 0; d0 < DN; d0 += TD) {
        // Load W tile -> As[d][k]  (transpose-on-store)
        #pragma unroll
        for (int r = 0; r < 4; r++) {
            int i   = tid + r * 256;       // float4 index, 0..1023
            int k   = i >> 3;              // 8 float4 per k-row
            int dd4 = (i & 7) * 4;
            float4 v = *(const float4*)(w + (size_t)(k0 + k) * DN + d0 + dd4);
            As[dd4 + 0][k] = v.x;
            As[dd4 + 1][k] = v.y;
            As[dd4 + 2][k] = v.z;
            As[dd4 + 3][k] = v.w;
        }
        // Load X tile -> Bs[d][m]  (natural layout, one warp per row)
        #pragma unroll
        for (int r = 0; r < 4; r++) {
            int i  = tid + r * 256;
            int dd = i >> 5;               // 32 float4 per d-row
            int m4 = (i & 31) * 4;
            float4 v = *(const float4*)(Xb + (size_t)(d0 + dd) * HWN + m0 + m4);
            *(float4*)&Bs[dd][m4] = v;
        }
        __syncthreads();

        #pragma unroll
        for (int dd = 0; dd < TD; dd++) {
            float a[8], bb[8];
            *(float4*)&a[0]  = *(const float4*)&As[dd][ty * 8];
            *(float4*)&a[4]  = *(const float4*)&As[dd][ty * 8 + 4];
            *(float4*)&bb[0] = *(const float4*)&Bs[dd][tx * 8];
            *(float4*)&bb[4] = *(const float4*)&Bs[dd][tx * 8 + 4];
            #pragma unroll
            for (int i = 0; i < 8; i++)
                #pragma unroll
                for (int j = 0; j < 8; j++)
                    acc[i][j] = fmaf(a[i], bb[j], acc[i][j]);
        }
        __syncthreads();
    }

    // Epilogue: score + local argmin over this CTA's 8 k-values per m-column
    float x2v[8], w2v[8];
    #pragma unroll
    for (int j = 0; j < 8; j++) x2v[j] = g_x2[b * HWN + m0 + tx * 8 + j];
    #pragma unroll
    for (int i = 0; i < 8; i++) w2v[i] = g_w2[k0 + ty * 8 + i];

    unsigned long long bestp[8];
    #pragma unroll
    for (int j = 0; j < 8; j++) {
        unsigned long long bp = 0xFFFFFFFFFFFFFFFFULL;
        #pragma unroll
        for (int i = 0; i < 8; i++) {
            // Mimic reference association: (x2 - 2*dot) + w2, no FMA contraction
            float d2 = __fadd_rn(__fsub_rn(x2v[j], __fmul_rn(2.0f, acc[i][j])), w2v[i]);
            unsigned int bits = __float_as_uint(d2);
            bits = (bits & 0x80000000u) ? ~bits : (bits | 0x80000000u);  // monotone key
            unsigned long long p =
                ((unsigned long long)bits << 32) | (unsigned int)(k0 + ty * 8 + i);
            bp = min(bp, p);
        }
        bestp[j] = bp;
    }

    __syncthreads();
    // Reuse As storage (16896B >= 16*128*8B) for cross-ty reduction
    unsigned long long* red = (unsigned long long*)&As[0][0];
    #pragma unroll
    for (int j = 0; j < 8; j++) red[ty * TM + tx * 8 + j] = bestp[j];
    __syncthreads();

    if (tid < TM) {
        unsigned long long bp = red[tid];
        #pragma unroll
        for (int r = 1; r < 16; r++) {
            unsigned long long v = red[r * TM + tid];
            bp = min(bp, v);
        }
        atomicMin(&g_best[b * HWN + m0 + tid], bp);
    }
}

// ---------------------------------------------------------------------------
// Gather: out[b,d,hw] = weight[idx[n], d], smem-staged transpose so both
// codebook reads and output writes are coalesced.
__global__ void vq_gather(const float* __restrict__ w, float* __restrict__ out) {
    __shared__ float codes[32][DN + 1];  // +1 pad: conflict-free column reads
    const int b   = blockIdx.y;
    const int hw0 = blockIdx.x * 32;
    const int tid = threadIdx.x;  // 256 threads

    // Phase 1: load 32 code rows (d = tid, row = s); coalesced reads of weight
    for (int s = 0; s < 32; s++) {
        unsigned int idx = (unsigned int)(g_best[b * HWN + hw0 + s] & 0xFFFFFFFFu);
        codes[s][tid] = w[(size_t)idx * DN + tid];
    }
    __syncthreads();

    // Phase 2: write out[b, d, hw0+c] with c = lane -> contiguous 128B stores
    const int c    = tid & 31;
    const int dgrp = tid >> 5;  // 8 d-rows per step
    float* ob = out + (size_t)b * DN * HWN + hw0;
    for (int d = dgrp; d < DN; d += 8) {
        ob[(size_t)d * HWN + c] = codes[c][d];
    }
}

// ---------------------------------------------------------------------------
extern "C" void kernel_launch(void* const* d_in, const int* in_sizes, int n_in,
                              void* d_out, int out_size) {
    const float* x = (const float*)d_in[0];   // [32,256,32,32] fp32
    const float* w = (const float*)d_in[1];   // [1024,256] fp32
    float* out = (float*)d_out;               // [32,256,32,32] fp32

    vq_init_best<<<NN / 256, 256>>>();
    vq_w2<<<KN / 8, 256>>>(w);
    {
        dim3 g(HWN / 256, BN);
        vq_x2<<<g, 256>>>(x);
    }
    {
        dim3 g(HWN / TM, KN / TK, BN);  // 8 x 8 x 32 = 2048 CTAs
        vq_main<<<g, 256>>>(x, w);
    }
    {
        dim3 g(HWN / 32, BN);           // 32 x 32 = 1024 CTAs
        vq_gather<<<g, 256>>>(w, out);
    }
}

// round 9
// speedup vs baseline: 2.2739x; 2.2739x over previous
#include <cuda_runtime.h>
#include <cuda_bf16.h>
#include <cstdint>

// Problem constants
#define BN   32
#define DN   256
#define KN   1024
#define HWN  1024
#define NN   32768

#define CAND_MAX 24      // final per-query candidates for exact rescore
#define LIST_CAP 48      // per-chunk emission list cap (smem)
#define MARGIN   4.0e-3f // > 2x worst-case bf16 d2 error (~1.6e-3)

#define PRB 528          // padded bf16 tile row stride in bytes (256*2 + 16)

// ---------------------------------------------------------------------------
// Device-global scratch (no allocation allowed)
__device__ unsigned long long g_best[NN];
__device__ float g_w2[KN];
__device__ float g_x2[NN];
__device__ __nv_bfloat16 g_wb[KN * DN];   // codebook bf16 [k][d]
__device__ __nv_bfloat16 g_xb[NN * DN];   // x transposed bf16 [n][d]
__device__ float g_xt[NN * DN];           // x transposed fp32 [n][d]
__device__ int g_ccnt[NN];
__device__ unsigned int g_cand[NN * CAND_MAX];

// ---------------------------------------------------------------------------
// Warp-level bf16 MMA (sm_80+ baseline; compiles on sm_103 base target)
__device__ __forceinline__ void mma16816(float* c, uint32_t a0, uint32_t a1,
                                         uint32_t a2, uint32_t a3,
                                         uint32_t b0, uint32_t b1) {
    asm volatile(
        "mma.sync.aligned.m16n8k16.row.col.f32.bf16.bf16.f32 "
        "{%0,%1,%2,%3}, {%4,%5,%6,%7}, {%8,%9}, {%0,%1,%2,%3};"
        : "+f"(c[0]), "+f"(c[1]), "+f"(c[2]), "+f"(c[3])
        : "r"(a0), "r"(a1), "r"(a2), "r"(a3), "r"(b0), "r"(b1));
}

// ---------------------------------------------------------------------------
// w2[k] = sum_d w[k,d]^2 (square-then-add, matching reference)
__global__ void vq_w2(const float* __restrict__ w) {
    int k = blockIdx.x * 8 + (threadIdx.x >> 5);
    int lane = threadIdx.x & 31;
    if (k >= KN) return;
    const float* row = w + (size_t)k * DN;
    float s = 0.f;
    #pragma unroll
    for (int d = lane; d < DN; d += 32) {
        float v = row[d];
        s = __fadd_rn(s, __fmul_rn(v, v));
    }
    #pragma unroll
    for (int o = 16; o > 0; o >>= 1) s += __shfl_xor_sync(0xffffffffu, s, o);
    if (lane == 0) g_w2[k] = s;
}

// x2[n] = sum_d x[b,d,hw]^2
__global__ void vq_x2(const float* __restrict__ x) {
    int b  = blockIdx.y;
    int hw = blockIdx.x * blockDim.x + threadIdx.x;
    const float* base = x + (size_t)b * DN * HWN + hw;
    float s = 0.f;
    #pragma unroll 8
    for (int d = 0; d < DN; d++) {
        float v = base[(size_t)d * HWN];
        s = __fadd_rn(s, __fmul_rn(v, v));
    }
    g_x2[b * HWN + hw] = s;
}

// Codebook fp32 -> bf16
__global__ void vq_wb(const float* __restrict__ w) {
    int i = (blockIdx.x * 256 + threadIdx.x) * 4;
    float4 v = *(const float4*)(w + i);
    __nv_bfloat16* o = g_wb + i;
    o[0] = __float2bfloat16(v.x);
    o[1] = __float2bfloat16(v.y);
    o[2] = __float2bfloat16(v.z);
    o[3] = __float2bfloat16(v.w);
}

// Transpose x[b][d][hw] -> Xt[n][d] (fp32 and bf16), n = b*HWN + hw
__global__ void vq_xt(const float* __restrict__ x) {
    __shared__ float t[32][33];
    int b   = blockIdx.z;
    int d0  = blockIdx.y * 32;
    int hw0 = blockIdx.x * 32;
    int tx = threadIdx.x, ty = threadIdx.y;  // 32 x 8
    #pragma unroll
    for (int r = 0; r < 4; r++)
        t[ty + 8 * r][tx] = x[(size_t)b * DN * HWN + (size_t)(d0 + ty + 8 * r) * HWN + hw0 + tx];
    __syncthreads();
    #pragma unroll
    for (int r = 0; r < 4; r++) {
        int n = b * HWN + hw0 + ty + 8 * r;
        float v = t[tx][ty + 8 * r];
        g_xt[(size_t)n * DN + d0 + tx] = v;
        g_xb[(size_t)n * DN + d0 + tx] = __float2bfloat16(v);
    }
}

// ---------------------------------------------------------------------------
// P1: bf16 HMMA approx-d2 + candidate filtering.
// Grid 256 CTAs (128 queries each), 256 threads (8 warps; warp -> 16 query rows).
// smem layout (bytes):
#define SA     0        // A tile: 128 rows x PRB          (67584)
#define SB     67584    // B tile: 128 rows x PRB          (67584)
#define SW2    135168   // w2: 1024 floats                 (4096)
#define SCMIN  139264   // per-query running min: 128 f    (512)
#define SCCNT  139776   // per-query list count: 128 int   (512)
#define SLIST  140288   // cand lists: 128 * 48 * 8B       (49152)
#define SMEM_P1 189440

__global__ __launch_bounds__(256, 1) void vq_p1() {
    extern __shared__ __align__(16) char smem[];
    char*  A    = smem + SA;
    char*  B    = smem + SB;
    float* w2s  = (float*)(smem + SW2);
    float* cmin = (float*)(smem + SCMIN);
    int*   ccnt = (int*)(smem + SCCNT);
    uint2* clist = (uint2*)(smem + SLIST);

    const int tid  = threadIdx.x;
    const int wid  = tid >> 5, lane = tid & 31;
    const int gid  = lane >> 2, tq = lane & 3;
    const int warpM = wid * 16;
    const int m0   = blockIdx.x * 128;

    // Fill A tile (queries m0..m0+127, bf16, padded rows)
    {
        const uint4* asrc = (const uint4*)(g_xb + (size_t)m0 * DN);
        #pragma unroll
        for (int i = tid; i < 4096; i += 256) {
            int r = i >> 5, c = i & 31;
            *(uint4*)(A + r * PRB + c * 16) = asrc[i];
        }
    }
    for (int i = tid; i < KN; i += 256) w2s[i] = g_w2[i];
    if (tid < 128) { cmin[tid] = 3.4e38f; ccnt[tid] = 0; }
    __syncthreads();

    const float x2r0 = g_x2[m0 + warpM + gid];
    const float x2r1 = g_x2[m0 + warpM + gid + 8];
    const int r0 = warpM + gid, r1 = r0 + 8;

    const char* Arow = A + (size_t)r0 * PRB + tq * 4;
    const char* Brow = B + (size_t)gid * PRB + tq * 4;

    for (int c = 0; c < 8; c++) {
        // Fill B tile (codes c*128 .. +127)
        const uint4* bsrc = (const uint4*)(g_wb + (size_t)c * 128 * DN);
        #pragma unroll
        for (int i = tid; i < 4096; i += 256) {
            int r = i >> 5, cc = i & 31;
            *(uint4*)(B + r * PRB + cc * 16) = bsrc[i];
        }
        __syncthreads();

        float acc[16][4];
        #pragma unroll
        for (int nt = 0; nt < 16; nt++)
            acc[nt][0] = acc[nt][1] = acc[nt][2] = acc[nt][3] = 0.f;

        #pragma unroll
        for (int ks = 0; ks < 16; ks++) {
            const int k2 = ks * 32;  // byte offset of k-step
            uint32_t a0 = *(const uint32_t*)(Arow + k2);
            uint32_t a1 = *(const uint32_t*)(Arow + 8 * PRB + k2);
            uint32_t a2 = *(const uint32_t*)(Arow + k2 + 16);
            uint32_t a3 = *(const uint32_t*)(Arow + 8 * PRB + k2 + 16);
            #pragma unroll
            for (int nt = 0; nt < 16; nt++) {
                uint32_t b0 = *(const uint32_t*)(Brow + nt * 8 * PRB + k2);
                uint32_t b1 = *(const uint32_t*)(Brow + nt * 8 * PRB + k2 + 16);
                mma16816(acc[nt], a0, a1, a2, a3, b0, b1);
            }
        }

        // Epilogue: approx d2, per-row chunk min, candidate emission
        float mn0 = 3.4e38f, mn1 = 3.4e38f;
        #pragma unroll
        for (int nt = 0; nt < 16; nt++) {
            int col = c * 128 + nt * 8 + tq * 2;
            float w20 = w2s[col], w21 = w2s[col + 1];
            float d00 = fmaf(-2.f, acc[nt][0], x2r0) + w20;
            float d01 = fmaf(-2.f, acc[nt][1], x2r0) + w21;
            float d10 = fmaf(-2.f, acc[nt][2], x2r1) + w20;
            float d11 = fmaf(-2.f, acc[nt][3], x2r1) + w21;
            acc[nt][0] = d00; acc[nt][1] = d01; acc[nt][2] = d10; acc[nt][3] = d11;
            mn0 = fminf(mn0, fminf(d00, d01));
            mn1 = fminf(mn1, fminf(d10, d11));
        }
        mn0 = fminf(mn0, __shfl_xor_sync(0xffffffffu, mn0, 1));
        mn0 = fminf(mn0, __shfl_xor_sync(0xffffffffu, mn0, 2));
        mn1 = fminf(mn1, __shfl_xor_sync(0xffffffffu, mn1, 1));
        mn1 = fminf(mn1, __shfl_xor_sync(0xffffffffu, mn1, 2));
        if (tq == 0) {
            cmin[r0] = fminf(cmin[r0], mn0);
            cmin[r1] = fminf(cmin[r1], mn1);
        }
        const float thr0 = mn0 + MARGIN, thr1 = mn1 + MARGIN;
        #pragma unroll
        for (int nt = 0; nt < 16; nt++) {
            int col = c * 128 + nt * 8 + tq * 2;
            if (acc[nt][0] <= thr0) {
                int p = atomicAdd(&ccnt[r0], 1);
                if (p < LIST_CAP) clist[r0 * LIST_CAP + p] = make_uint2(__float_as_uint(acc[nt][0]), col);
            }
            if (acc[nt][1] <= thr0) {
                int p = atomicAdd(&ccnt[r0], 1);
                if (p < LIST_CAP) clist[r0 * LIST_CAP + p] = make_uint2(__float_as_uint(acc[nt][1]), col + 1);
            }
            if (acc[nt][2] <= thr1) {
                int p = atomicAdd(&ccnt[r1], 1);
                if (p < LIST_CAP) clist[r1 * LIST_CAP + p] = make_uint2(__float_as_uint(acc[nt][2]), col);
            }
            if (acc[nt][3] <= thr1) {
                int p = atomicAdd(&ccnt[r1], 1);
                if (p < LIST_CAP) clist[r1 * LIST_CAP + p] = make_uint2(__float_as_uint(acc[nt][3]), col + 1);
            }
        }
        __syncthreads();  // protects B refill AND final list read
    }

    // Final filter: keep only candidates within margin of the GLOBAL approx min
    if (tid < 128) {
        int m = m0 + tid;
        float thr = cmin[tid] + MARGIN;
        int n = ccnt[tid]; if (n > LIST_CAP) n = LIST_CAP;
        int out = 0;
        for (int i = 0; i < n; i++) {
            uint2 e = clist[tid * LIST_CAP + i];
            if (__uint_as_float(e.x) <= thr && out < CAND_MAX)
                g_cand[(size_t)m * CAND_MAX + (out++)] = e.y;
        }
        g_ccnt[m] = out;
    }
}

// ---------------------------------------------------------------------------
// P3: exact fp32 rescore of candidates. One warp per query.
__global__ __launch_bounds__(256) void vq_p3(const float* __restrict__ w) {
    const int wid = threadIdx.x >> 5, lane = threadIdx.x & 31;
    const int q = blockIdx.x * 8 + wid;
    int cnt = g_ccnt[q];
    if (cnt > CAND_MAX) cnt = CAND_MAX;
    const float* xr = g_xt + (size_t)q * DN;
    const float x2v = g_x2[q];
    unsigned long long best = 0xFFFFFFFFFFFFFFFFULL;
    for (int c = 0; c < cnt; c++) {
        unsigned int k = g_cand[(size_t)q * CAND_MAX + c];
        const float* wr = w + (size_t)k * DN;
        float s = 0.f;
        #pragma unroll
        for (int d = lane; d < DN; d += 32)
            s = fmaf(xr[d], wr[d], s);
        #pragma unroll
        for (int o = 16; o > 0; o >>= 1) s += __shfl_xor_sync(0xffffffffu, s, o);
        // Reference association: (x2 - 2*dot) + w2
        float d2 = __fadd_rn(__fsub_rn(x2v, __fmul_rn(2.0f, s)), g_w2[k]);
        unsigned int bits = __float_as_uint(d2);
        bits = (bits & 0x80000000u) ? ~bits : (bits | 0x80000000u);
        unsigned long long p = ((unsigned long long)bits << 32) | k;
        best = min(best, p);
    }
    if (lane == 0) g_best[q] = best;
}

// ---------------------------------------------------------------------------
// Gather: out[b,d,hw] = weight[idx[n], d]
__global__ void vq_gather(const float* __restrict__ w, float* __restrict__ out) {
    __shared__ float codes[32][DN + 1];
    const int b   = blockIdx.y;
    const int hw0 = blockIdx.x * 32;
    const int tid = threadIdx.x;  // 256
    for (int s = 0; s < 32; s++) {
        unsigned int idx = (unsigned int)(g_best[b * HWN + hw0 + s] & 0xFFFFFFFFu);
        codes[s][tid] = w[(size_t)idx * DN + tid];
    }
    __syncthreads();
    const int c    = tid & 31;
    const int dgrp = tid >> 5;
    float* ob = out + (size_t)b * DN * HWN + hw0;
    for (int d = dgrp; d < DN; d += 8)
        ob[(size_t)d * HWN + c] = codes[c][d];
}

// ---------------------------------------------------------------------------
extern "C" void kernel_launch(void* const* d_in, const int* in_sizes, int n_in,
                              void* d_out, int out_size) {
    const float* x = (const float*)d_in[0];   // [32,256,32,32] fp32
    const float* w = (const float*)d_in[1];   // [1024,256] fp32
    float* out = (float*)d_out;

    cudaFuncSetAttribute(vq_p1, cudaFuncAttributeMaxDynamicSharedMemorySize, SMEM_P1);

    vq_w2<<<KN / 8, 256>>>(w);
    {
        dim3 g(HWN / 256, BN);
        vq_x2<<<g, 256>>>(x);
    }
    vq_wb<<<KN * DN / 1024, 256>>>(w);
    {
        dim3 g(HWN / 32, DN / 32, BN);
        dim3 blk(32, 8);
        vq_xt<<<g, blk>>>(x);
    }
    vq_p1<<<NN / 128, 256, SMEM_P1>>>();
    vq_p3<<<NN / 8, 256>>>(w);
    {
        dim3 g(HWN / 32, BN);
        vq_gather<<<g, 256>>>(w, out);
    }
}